// round 9
// baseline (speedup 1.0000x reference)
#include <cuda_runtime.h>
#include <cuda_fp16.h>
#include <cstdint>

#define N_DIM 2048
#define H_DIM 2048
#define V_DIM 32000

// ---- scratch ----
__device__ __half g_xh[(size_t)N_DIM * H_DIM];   // 8 MB (x in f16)
__device__ double g_acc;

// ============================================================
// Kernel 1: fp32 -> fp16 conversion for x only; zero accumulator
// ============================================================
__global__ void convert_x_kernel(const float* __restrict__ x) {
    size_t tid = (size_t)blockIdx.x * blockDim.x + threadIdx.x;
    size_t stride = (size_t)gridDim.x * blockDim.x;
    if (tid == 0) g_acc = 0.0;

    const size_t nx4 = (size_t)N_DIM * H_DIM / 4;
    const float4* x4 = (const float4*)x;
    for (size_t i = tid; i < nx4; i += stride) {
        float4 v = x4[i];
        __half2* dst = (__half2*)(g_xh + i * 4);
        dst[0] = __floats2half2_rn(v.x, v.y);
        dst[1] = __floats2half2_rn(v.z, v.w);
    }
}

// ============================================================
// Kernel 2: fused W(f32)->f16 convert + fp16 HMMA GEMM + MSE reduce
//   CTA tile 256x128, BK=64; 8 warps (4 M x 2 N), warp tile 64x64
//   A: cp.async f16 (pre-converted x), 2 stages
//   B: cp.async f32 W -> smem staging (272B row pitch) -> cvt -> f16 swizzled
// ============================================================
#define BM 256
#define BN 128
#define BK 64
#define NK (H_DIM / BK)               // 32
#define THREADS 256
#define A_BYTES (BM * BK * 2)         // 32768, f16 rows of 128B, swizzled
#define BF32_PITCH 272                // 256B data + 16B pad (bank rotation)
#define BF32_BYTES (BN * BF32_PITCH)  // 34816
#define STAGE_BYTES (A_BYTES + BF32_BYTES)   // 67584
#define BF16_OFF (2 * STAGE_BYTES)           // 135168
#define BF16_BYTES (BN * BK * 2)      // 16384
#define SMEM_BYTES (BF16_OFF + BF16_BYTES)   // 151552

__device__ __forceinline__ void cp_async16(uint32_t smem_addr, const void* gptr) {
    asm volatile("cp.async.cg.shared.global [%0], [%1], 16;"
                 :: "r"(smem_addr), "l"(gptr));
}

__global__ void __launch_bounds__(THREADS)
gemm_mse_kernel(const float* __restrict__ W, const float* __restrict__ y) {
    extern __shared__ __align__(1024) char smem[];
    __shared__ float red[8];

    const int tid = threadIdx.x;
    const int lane = tid & 31;
    const int warp = tid >> 5;
    const int warp_m = warp & 3;   // 0..3 -> 64-row slabs (M)
    const int warp_n = warp >> 2;  // 0..1 -> 64-col slabs (N)

    const uint32_t sbase = (uint32_t)__cvta_generic_to_shared(smem);

    const int n_blk = blockIdx.x * BM;
    const int v_blk = blockIdx.y * BN;
    const __half* gA = g_xh + (size_t)n_blk * H_DIM;
    const float* gB = W + (size_t)v_blk * H_DIM;

    // ---- loaders ----
    // A: 2048 16B-chunks (8/thread), f16 swizzled rows of 128B
    // B: 2048 16B-chunks (8/thread), f32 linear rows with 272B pitch
    auto issue_tile = [&](int kt) {
        const uint32_t st = sbase + (kt & 1) * STAGE_BYTES;
        const __half* gAk = gA + kt * BK;
        const float* gBk = gB + kt * BK;
        #pragma unroll
        for (int i = 0; i < 8; i++) {
            int chunk = i * THREADS + tid;   // 0..2047
            int row = chunk >> 3;            // 0..255
            int c16 = chunk & 7;
            uint32_t off = (uint32_t)(row * 128 + ((c16 ^ (row & 7)) * 16));
            cp_async16(st + off, gAk + (size_t)row * H_DIM + c16 * 8);
        }
        #pragma unroll
        for (int i = 0; i < 8; i++) {
            int chunk = i * THREADS + tid;   // 0..2047
            int row = chunk >> 4;            // 0..127
            int c16 = chunk & 15;            // 16 chunks of 16B per 256B row
            uint32_t off = (uint32_t)(row * BF32_PITCH + c16 * 16);
            cp_async16(st + A_BYTES + off, gBk + (size_t)row * H_DIM + c16 * 4);
        }
        asm volatile("cp.async.commit_group;");
    };

    issue_tile(0);

    // f16x2 accumulators
    uint32_t c[4][8][2];
    #pragma unroll
    for (int mi = 0; mi < 4; mi++)
        #pragma unroll
        for (int ni = 0; ni < 8; ni++) { c[mi][ni][0] = 0u; c[mi][ni][1] = 0u; }

    const int a_row_base = warp_m * 64 + (lane & 15);
    const int a_kc_lane = lane >> 4;                  // 0/1
    const int b_row_base = warp_n * 64 + (lane & 7) + ((lane >> 4) << 3);
    const int b_kc_lane = (lane >> 3) & 1;

    // convert-thread mapping: row = tid>>1, half h = tid&1
    const int cv_row = tid >> 1;
    const int cv_h = tid & 1;
    const uint32_t bf16 = sbase + BF16_OFF;

    for (int kt = 0; kt < NK; kt++) {
        asm volatile("cp.async.wait_group 0;");
        __syncthreads();
        if (kt + 1 < NK) issue_tile(kt + 1);

        const uint32_t aBase = sbase + (kt & 1) * STAGE_BYTES;
        const uint32_t bf32 = aBase + A_BYTES;

        // ---- convert B f32 stage -> f16 swizzled buffer ----
        {
            const char* src = smem + (bf32 - sbase) + cv_row * BF32_PITCH + cv_h * 128;
            float4 v[8];
            #pragma unroll
            for (int j = 0; j < 8; j++)
                v[j] = *(const float4*)(src + j * 16);
            #pragma unroll
            for (int jj = 0; jj < 4; jj++) {
                __half2 h0 = __floats2half2_rn(v[2 * jj].x, v[2 * jj].y);
                __half2 h1 = __floats2half2_rn(v[2 * jj].z, v[2 * jj].w);
                __half2 h2 = __floats2half2_rn(v[2 * jj + 1].x, v[2 * jj + 1].y);
                __half2 h3 = __floats2half2_rn(v[2 * jj + 1].z, v[2 * jj + 1].w);
                int cq = cv_h * 4 + jj;
                uint32_t off = (uint32_t)(cv_row * 128 + ((cq ^ (cv_row & 7)) * 16));
                uint4 pack;
                pack.x = *(uint32_t*)&h0; pack.y = *(uint32_t*)&h1;
                pack.z = *(uint32_t*)&h2; pack.w = *(uint32_t*)&h3;
                *(uint4*)(smem + BF16_OFF + off) = pack;
            }
        }
        __syncthreads();

        // ---- mma over 4 k16-steps ----
        #pragma unroll
        for (int ks = 0; ks < 4; ks++) {
            uint32_t a[4][4];
            #pragma unroll
            for (int mi = 0; mi < 4; mi++) {
                int row = a_row_base + mi * 16;
                int kc = ks * 2 + a_kc_lane;
                uint32_t addr = aBase + (uint32_t)(row * 128 + ((kc ^ (row & 7)) * 16));
                asm volatile(
                    "ldmatrix.sync.aligned.m8n8.x4.shared.b16 {%0,%1,%2,%3}, [%4];"
                    : "=r"(a[mi][0]), "=r"(a[mi][1]), "=r"(a[mi][2]), "=r"(a[mi][3])
                    : "r"(addr));
            }
            uint32_t b[4][4];
            #pragma unroll
            for (int p = 0; p < 4; p++) {
                int row = b_row_base + p * 16;
                int kc = ks * 2 + b_kc_lane;
                uint32_t addr = bf16 + (uint32_t)(row * 128 + ((kc ^ (row & 7)) * 16));
                asm volatile(
                    "ldmatrix.sync.aligned.m8n8.x4.shared.b16 {%0,%1,%2,%3}, [%4];"
                    : "=r"(b[p][0]), "=r"(b[p][1]), "=r"(b[p][2]), "=r"(b[p][3])
                    : "r"(addr));
            }
            #pragma unroll
            for (int mi = 0; mi < 4; mi++) {
                #pragma unroll
                for (int ni = 0; ni < 8; ni++) {
                    int p = ni >> 1;
                    int o = (ni & 1) * 2;
                    asm volatile(
                        "mma.sync.aligned.m16n8k16.row.col.f16.f16.f16.f16 "
                        "{%0,%1}, {%2,%3,%4,%5}, {%6,%7}, {%0,%1};"
                        : "+r"(c[mi][ni][0]), "+r"(c[mi][ni][1])
                        : "r"(a[mi][0]), "r"(a[mi][1]), "r"(a[mi][2]), "r"(a[mi][3]),
                          "r"(b[p][o]), "r"(b[p][o + 1]));
                }
            }
        }
    }

    // ---- epilogue: (logit - y)^2 ----
    const int gr = lane >> 2;
    const int gc = (lane & 3) * 2;
    float acc = 0.0f;
    #pragma unroll
    for (int mi = 0; mi < 4; mi++) {
        int gn0 = n_blk + warp_m * 64 + mi * 16 + gr;
        const float* y0 = y + (size_t)gn0 * V_DIM + v_blk;
        const float* y8 = y0 + (size_t)8 * V_DIM;
        #pragma unroll
        for (int ni = 0; ni < 8; ni++) {
            int col = warp_n * 64 + ni * 8 + gc;
            float2 y01 = *(const float2*)(y0 + col);
            float2 y23 = *(const float2*)(y8 + col);
            float2 c01 = __half22float2(*(__half2*)&c[mi][ni][0]);
            float2 c23 = __half22float2(*(__half2*)&c[mi][ni][1]);
            float d0 = c01.x - y01.x;
            float d1 = c01.y - y01.y;
            float d2 = c23.x - y23.x;
            float d3 = c23.y - y23.y;
            acc += d0 * d0 + d1 * d1 + d2 * d2 + d3 * d3;
        }
    }
    #pragma unroll
    for (int off = 16; off; off >>= 1)
        acc += __shfl_xor_sync(0xFFFFFFFFu, acc, off);
    if (lane == 0) red[warp] = acc;
    __syncthreads();
    if (warp == 0) {
        float sv = (lane < 8) ? red[lane] : 0.0f;
        #pragma unroll
        for (int off = 4; off; off >>= 1)
            sv += __shfl_xor_sync(0xFFFFFFFFu, sv, off);
        if (lane == 0) atomicAdd(&g_acc, (double)sv);
    }
}

// ============================================================
// Kernel 3: finalize
// ============================================================
__global__ void finalize_kernel(float* out) {
    out[0] = (float)(g_acc / ((double)N_DIM * (double)V_DIM));
}

// ============================================================
extern "C" void kernel_launch(void* const* d_in, const int* in_sizes, int n_in,
                              void* d_out, int out_size) {
    (void)in_sizes; (void)n_in; (void)out_size;
    const float* x = (const float*)d_in[0];   // [N, H]
    const float* y = (const float*)d_in[1];   // [N, V]
    const float* W = (const float*)d_in[2];   // [V, H]
    float* out = (float*)d_out;

    static bool attr_set = false;
    if (!attr_set) {
        cudaFuncSetAttribute(gemm_mse_kernel,
                             cudaFuncAttributeMaxDynamicSharedMemorySize,
                             SMEM_BYTES);
        attr_set = true;
    }

    convert_x_kernel<<<512, 256>>>(x);

    dim3 grid(N_DIM / BM, V_DIM / BN);  // (8, 250): x-fastest -> W stripe L2 reuse
    gemm_mse_kernel<<<grid, THREADS, SMEM_BYTES>>>(W, y);

    finalize_kernel<<<1, 1>>>(out);
}

// round 10
// speedup vs baseline: 1.1885x; 1.1885x over previous
#include <cuda_runtime.h>
#include <cuda_fp16.h>
#include <cstdint>

#define N_DIM 2048
#define H_DIM 2048
#define V_DIM 32000

// ---- scratch ----
__device__ __half g_xh[(size_t)N_DIM * H_DIM];   // 8 MB (x in f16)
__device__ double g_acc;
__device__ unsigned g_count = 0;

// ============================================================
// Kernel 1: fp32 -> fp16 conversion for x; zero accumulator
// ============================================================
__global__ void convert_x_kernel(const float* __restrict__ x) {
    size_t tid = (size_t)blockIdx.x * blockDim.x + threadIdx.x;
    size_t stride = (size_t)gridDim.x * blockDim.x;
    if (tid == 0) g_acc = 0.0;

    const size_t nx4 = (size_t)N_DIM * H_DIM / 4;
    const float4* x4 = (const float4*)x;
    for (size_t i = tid; i < nx4; i += stride) {
        float4 v = x4[i];
        __half2* dst = (__half2*)(g_xh + i * 4);
        dst[0] = __floats2half2_rn(v.x, v.y);
        dst[1] = __floats2half2_rn(v.z, v.w);
    }
}

// ============================================================
// Kernel 2: fp16 HMMA GEMM with register-staged W f32->f16 convert
//   CTA 256x128, BK=64; 8 warps (4 M x 2 N), warp tile 64x64
//   A: cp.async f16 double-buffered; B: LDG f32 regs -> cvt -> STS f16 (dbuf)
//   One __syncthreads per k-tile. Fused MSE reduce + last-CTA finalize.
// ============================================================
#define BM 256
#define BN 128
#define BK 64
#define NK (H_DIM / BK)               // 32
#define THREADS 256
#define A_BYTES (BM * BK * 2)         // 32768 per stage
#define B_BYTES (BN * BK * 2)         // 16384 per stage
#define BOFF (2 * A_BYTES)            // 65536
#define SMEM_BYTES (BOFF + 2 * B_BYTES)    // 98304
#define NUM_CTAS ((N_DIM / BM) * (V_DIM / BN))   // 2000

__device__ __forceinline__ void cp_async16(uint32_t smem_addr, const void* gptr) {
    asm volatile("cp.async.cg.shared.global [%0], [%1], 16;"
                 :: "r"(smem_addr), "l"(gptr));
}

__global__ void __launch_bounds__(THREADS)
gemm_mse_kernel(const float* __restrict__ W, const float* __restrict__ y,
                float* __restrict__ out) {
    extern __shared__ __align__(1024) char smem[];
    __shared__ float red[8];

    const int tid = threadIdx.x;
    const int lane = tid & 31;
    const int warp = tid >> 5;
    const int warp_m = warp & 3;   // 0..3 -> 64-row slabs (M)
    const int warp_n = warp >> 2;  // 0..1 -> 64-col slabs (N)

    const uint32_t sbase = (uint32_t)__cvta_generic_to_shared(smem);

    const int n_blk = blockIdx.x * BM;
    const int v_blk = blockIdx.y * BN;
    const __half* gA = g_xh + (size_t)n_blk * H_DIM;
    const float* gB = W + (size_t)v_blk * H_DIM;

    // ---- A loader: 2048 16B-chunks (8/thread), swizzled 128B rows ----
    auto issue_A = [&](int kt) {
        const uint32_t st = sbase + (kt & 1) * A_BYTES;
        const __half* gAk = gA + kt * BK;
        #pragma unroll
        for (int i = 0; i < 8; i++) {
            int chunk = i * THREADS + tid;   // 0..2047
            int row = chunk >> 3;            // 0..255
            int c16 = chunk & 7;
            uint32_t off = (uint32_t)(row * 128 + ((c16 ^ (row & 7)) * 16));
            cp_async16(st + off, gAk + (size_t)row * H_DIM + c16 * 8);
        }
        asm volatile("cp.async.commit_group;");
    };

    // ---- B register staging: 8 float4 per thread per tile ----
    float4 wreg[8];
    auto ldg_B = [&](int kt) {
        const float* gBk = gB + kt * BK;
        #pragma unroll
        for (int i = 0; i < 8; i++) {
            int chunk = i * THREADS + tid;   // 0..2047
            int row = chunk >> 4;            // 0..127
            int c16 = chunk & 15;            // 16B fp32 chunks per 256B row
            wreg[i] = __ldg((const float4*)(gBk + (size_t)row * H_DIM + c16 * 4));
        }
    };
    auto sts_B = [&](int kt) {
        #pragma unroll
        for (int i = 0; i < 8; i++) {
            int chunk = i * THREADS + tid;
            int row = chunk >> 4;
            int c16 = chunk & 15;
            __half2 h0 = __floats2half2_rn(wreg[i].x, wreg[i].y);
            __half2 h1 = __floats2half2_rn(wreg[i].z, wreg[i].w);
            uint32_t off = (uint32_t)(row * 128 +
                           (((c16 >> 1) ^ (row & 7)) * 16) + (c16 & 1) * 8);
            uint2 v;
            v.x = *(uint32_t*)&h0;
            v.y = *(uint32_t*)&h1;
            *(uint2*)(smem + BOFF + (kt & 1) * B_BYTES + off) = v;
        }
    };

    // prologue
    ldg_B(0);
    issue_A(0);

    // f16x2 accumulators
    uint32_t c[4][8][2];
    #pragma unroll
    for (int mi = 0; mi < 4; mi++)
        #pragma unroll
        for (int ni = 0; ni < 8; ni++) { c[mi][ni][0] = 0u; c[mi][ni][1] = 0u; }

    const int a_row_base = warp_m * 64 + (lane & 15);
    const int a_kc_lane = lane >> 4;                  // 0/1
    const int b_row_base = warp_n * 64 + (lane & 7) + ((lane >> 4) << 3);
    const int b_kc_lane = (lane >> 3) & 1;

    for (int kt = 0; kt < NK; kt++) {
        // convert current W regs into f16 buffer (before the sync)
        sts_B(kt);
        if (kt + 1 < NK) {
            ldg_B(kt + 1);          // hidden under this tile's MMA phase
            issue_A(kt + 1);
            asm volatile("cp.async.wait_group 1;");
        } else {
            asm volatile("cp.async.wait_group 0;");
        }
        __syncthreads();

        const uint32_t aBase = sbase + (kt & 1) * A_BYTES;
        const uint32_t bBase = sbase + BOFF + (kt & 1) * B_BYTES;

        #pragma unroll
        for (int ks = 0; ks < 4; ks++) {
            uint32_t a[4][4];
            #pragma unroll
            for (int mi = 0; mi < 4; mi++) {
                int row = a_row_base + mi * 16;
                int kc = ks * 2 + a_kc_lane;
                uint32_t addr = aBase + (uint32_t)(row * 128 + ((kc ^ (row & 7)) * 16));
                asm volatile(
                    "ldmatrix.sync.aligned.m8n8.x4.shared.b16 {%0,%1,%2,%3}, [%4];"
                    : "=r"(a[mi][0]), "=r"(a[mi][1]), "=r"(a[mi][2]), "=r"(a[mi][3])
                    : "r"(addr));
            }
            uint32_t b[4][4];
            #pragma unroll
            for (int p = 0; p < 4; p++) {
                int row = b_row_base + p * 16;
                int kc = ks * 2 + b_kc_lane;
                uint32_t addr = bBase + (uint32_t)(row * 128 + ((kc ^ (row & 7)) * 16));
                asm volatile(
                    "ldmatrix.sync.aligned.m8n8.x4.shared.b16 {%0,%1,%2,%3}, [%4];"
                    : "=r"(b[p][0]), "=r"(b[p][1]), "=r"(b[p][2]), "=r"(b[p][3])
                    : "r"(addr));
            }
            #pragma unroll
            for (int mi = 0; mi < 4; mi++) {
                #pragma unroll
                for (int ni = 0; ni < 8; ni++) {
                    int p = ni >> 1;
                    int o = (ni & 1) * 2;
                    asm volatile(
                        "mma.sync.aligned.m16n8k16.row.col.f16.f16.f16.f16 "
                        "{%0,%1}, {%2,%3,%4,%5}, {%6,%7}, {%0,%1};"
                        : "+r"(c[mi][ni][0]), "+r"(c[mi][ni][1])
                        : "r"(a[mi][0]), "r"(a[mi][1]), "r"(a[mi][2]), "r"(a[mi][3]),
                          "r"(b[p][o]), "r"(b[p][o + 1]));
                }
            }
        }
        __syncthreads();   // B buffer (kt&1) reuse in kt+2; A stage reuse in kt+2
    }

    // ---- epilogue: (logit - y)^2 ----
    const int gr = lane >> 2;
    const int gc = (lane & 3) * 2;
    float acc = 0.0f;
    #pragma unroll
    for (int mi = 0; mi < 4; mi++) {
        int gn0 = n_blk + warp_m * 64 + mi * 16 + gr;
        const float* y0 = y + (size_t)gn0 * V_DIM + v_blk;
        const float* y8 = y0 + (size_t)8 * V_DIM;
        #pragma unroll
        for (int ni = 0; ni < 8; ni++) {
            int col = warp_n * 64 + ni * 8 + gc;
            float2 y01 = *(const float2*)(y0 + col);
            float2 y23 = *(const float2*)(y8 + col);
            float2 c01 = __half22float2(*(__half2*)&c[mi][ni][0]);
            float2 c23 = __half22float2(*(__half2*)&c[mi][ni][1]);
            float d0 = c01.x - y01.x;
            float d1 = c01.y - y01.y;
            float d2 = c23.x - y23.x;
            float d3 = c23.y - y23.y;
            acc += d0 * d0 + d1 * d1 + d2 * d2 + d3 * d3;
        }
    }
    #pragma unroll
    for (int off = 16; off; off >>= 1)
        acc += __shfl_xor_sync(0xFFFFFFFFu, acc, off);
    if (lane == 0) red[warp] = acc;
    __syncthreads();
    if (warp == 0) {
        float sv = (lane < 8) ? red[lane] : 0.0f;
        #pragma unroll
        for (int off = 4; off; off >>= 1)
            sv += __shfl_xor_sync(0xFFFFFFFFu, sv, off);
        if (lane == 0) {
            atomicAdd(&g_acc, (double)sv);
            __threadfence();
            unsigned done = atomicAdd(&g_count, 1u);
            if (done == NUM_CTAS - 1) {
                double total = atomicAdd(&g_acc, 0.0);   // ordered read
                out[0] = (float)(total / ((double)N_DIM * (double)V_DIM));
                g_count = 0;   // reset for next graph replay
            }
        }
    }
}

// ============================================================
extern "C" void kernel_launch(void* const* d_in, const int* in_sizes, int n_in,
                              void* d_out, int out_size) {
    (void)in_sizes; (void)n_in; (void)out_size;
    const float* x = (const float*)d_in[0];   // [N, H]
    const float* y = (const float*)d_in[1];   // [N, V]
    const float* W = (const float*)d_in[2];   // [V, H]
    float* out = (float*)d_out;

    static bool attr_set = false;
    if (!attr_set) {
        cudaFuncSetAttribute(gemm_mse_kernel,
                             cudaFuncAttributeMaxDynamicSharedMemorySize,
                             SMEM_BYTES);
        attr_set = true;
    }

    convert_x_kernel<<<512, 256>>>(x);

    dim3 grid(N_DIM / BM, V_DIM / BN);  // (8, 250): x-fastest -> W stripe L2 reuse
    gemm_mse_kernel<<<grid, THREADS, SMEM_BYTES>>>(W, y, out);
}

// round 11
// speedup vs baseline: 1.4736x; 1.2399x over previous
#include <cuda_runtime.h>
#include <cuda_fp16.h>
#include <cstdint>

#define N_DIM 2048
#define H_DIM 2048
#define V_DIM 32000

// ---- scratch ----
__device__ __half g_Wh[(size_t)V_DIM * H_DIM];   // 131 MB
__device__ __half g_xh[(size_t)N_DIM * H_DIM];   // 8 MB
__device__ double g_acc;
__device__ unsigned g_count = 0;

// ============================================================
// Kernel 1: fp32 -> fp16 conversion; zero accumulator
// ============================================================
__global__ void convert_kernel(const float* __restrict__ x,
                               const float* __restrict__ W) {
    size_t tid = (size_t)blockIdx.x * blockDim.x + threadIdx.x;
    size_t stride = (size_t)gridDim.x * blockDim.x;
    if (tid == 0) g_acc = 0.0;

    const size_t nW4 = (size_t)V_DIM * H_DIM / 4;
    const float4* W4 = (const float4*)W;
    for (size_t i = tid; i < nW4; i += stride) {
        float4 v = W4[i];
        __half2* dst = (__half2*)(g_Wh + i * 4);
        dst[0] = __floats2half2_rn(v.x, v.y);
        dst[1] = __floats2half2_rn(v.z, v.w);
    }
    const size_t nx4 = (size_t)N_DIM * H_DIM / 4;
    const float4* x4 = (const float4*)x;
    for (size_t i = tid; i < nx4; i += stride) {
        float4 v = x4[i];
        __half2* dst = (__half2*)(g_xh + i * 4);
        dst[0] = __floats2half2_rn(v.x, v.y);
        dst[1] = __floats2half2_rn(v.z, v.w);
    }
}

// ============================================================
// Kernel 2: fp16 HMMA GEMM (f16 acc), 2 CTAs/SM for latency hiding
//   CTA tile 128x128, BK=64; 8 warps (2 M x 4 N), warp tile 64x32
//   3-stage cp.async; fused MSE reduce + last-CTA finalize
// ============================================================
#define BM 128
#define BN 128
#define BK 64
#define NK (H_DIM / BK)               // 32
#define STAGES 3
#define A_BYTES (BM * BK * 2)         // 16384
#define B_BYTES (BN * BK * 2)         // 16384
#define STAGE_BYTES (A_BYTES + B_BYTES)    // 32768
#define SMEM_BYTES (STAGES * STAGE_BYTES)  // 98304 -> 2 CTAs = 192KB <= 228KB
#define THREADS 256
#define NUM_CTAS ((N_DIM / BM) * (V_DIM / BN))   // 4000

__device__ __forceinline__ void cp_async16(uint32_t smem_addr, const void* gptr) {
    asm volatile("cp.async.cg.shared.global [%0], [%1], 16;"
                 :: "r"(smem_addr), "l"(gptr));
}

__global__ void __launch_bounds__(THREADS, 2)
gemm_mse_kernel(const float* __restrict__ y, float* __restrict__ out) {
    extern __shared__ __align__(1024) char smem[];
    __shared__ float red[8];

    const int tid = threadIdx.x;
    const int lane = tid & 31;
    const int warp = tid >> 5;
    const int warp_m = warp & 1;   // 0..1 -> 64-row slabs (M)
    const int warp_n = warp >> 1;  // 0..3 -> 32-col slabs (N)

    const uint32_t sbase = (uint32_t)__cvta_generic_to_shared(smem);

    const int n_blk = blockIdx.x * BM;
    const int v_blk = blockIdx.y * BN;
    const __half* gA = g_xh + (size_t)n_blk * H_DIM;
    const __half* gB = g_Wh + (size_t)v_blk * H_DIM;

    // loader: 1024 16B-chunks per matrix (4/thread each)
    auto issue_tile = [&](int kt) {
        const uint32_t st = sbase + (kt % STAGES) * STAGE_BYTES;
        const __half* gAk = gA + kt * BK;
        const __half* gBk = gB + kt * BK;
        #pragma unroll
        for (int i = 0; i < 4; i++) {
            int chunk = i * THREADS + tid;   // 0..1023
            int row = chunk >> 3;            // 0..127
            int c16 = chunk & 7;
            uint32_t off = (uint32_t)(row * 128 + ((c16 ^ (row & 7)) * 16));
            cp_async16(st + off, gAk + (size_t)row * H_DIM + c16 * 8);
            cp_async16(st + A_BYTES + off, gBk + (size_t)row * H_DIM + c16 * 8);
        }
        asm volatile("cp.async.commit_group;");
    };

    issue_tile(0);
    issue_tile(1);

    // f16x2 accumulators: warp tile 64x32 -> 4 mi x 4 ni x 2 regs = 32 regs
    uint32_t c[4][4][2];
    #pragma unroll
    for (int mi = 0; mi < 4; mi++)
        #pragma unroll
        for (int ni = 0; ni < 4; ni++) { c[mi][ni][0] = 0u; c[mi][ni][1] = 0u; }

    // round-1-validated fragment addressing
    const int a_row_base = warp_m * 64 + (lane & 15);
    const int a_kc_lane = lane >> 4;                  // 0/1
    const int b_row_base = warp_n * 32 + (lane & 7) + ((lane >> 4) << 3);
    const int b_kc_lane = (lane >> 3) & 1;

    for (int kt = 0; kt < NK; kt++) {
        asm volatile("cp.async.wait_group 1;");
        __syncthreads();

        const uint32_t aBase = sbase + (kt % STAGES) * STAGE_BYTES;
        const uint32_t bBase = aBase + A_BYTES;

        #pragma unroll
        for (int ks = 0; ks < 4; ks++) {   // 4 x k16 per tile
            uint32_t a[4][4];
            #pragma unroll
            for (int mi = 0; mi < 4; mi++) {
                int row = a_row_base + mi * 16;
                int kc = ks * 2 + a_kc_lane;
                uint32_t addr = aBase + (uint32_t)(row * 128 + ((kc ^ (row & 7)) * 16));
                asm volatile(
                    "ldmatrix.sync.aligned.m8n8.x4.shared.b16 {%0,%1,%2,%3}, [%4];"
                    : "=r"(a[mi][0]), "=r"(a[mi][1]), "=r"(a[mi][2]), "=r"(a[mi][3])
                    : "r"(addr));
            }
            uint32_t b[2][4];
            #pragma unroll
            for (int p = 0; p < 2; p++) {
                int row = b_row_base + p * 16;
                int kc = ks * 2 + b_kc_lane;
                uint32_t addr = bBase + (uint32_t)(row * 128 + ((kc ^ (row & 7)) * 16));
                asm volatile(
                    "ldmatrix.sync.aligned.m8n8.x4.shared.b16 {%0,%1,%2,%3}, [%4];"
                    : "=r"(b[p][0]), "=r"(b[p][1]), "=r"(b[p][2]), "=r"(b[p][3])
                    : "r"(addr));
            }
            #pragma unroll
            for (int mi = 0; mi < 4; mi++) {
                #pragma unroll
                for (int ni = 0; ni < 4; ni++) {
                    int p = ni >> 1;
                    int o = (ni & 1) * 2;
                    asm volatile(
                        "mma.sync.aligned.m16n8k16.row.col.f16.f16.f16.f16 "
                        "{%0,%1}, {%2,%3,%4,%5}, {%6,%7}, {%0,%1};"
                        : "+r"(c[mi][ni][0]), "+r"(c[mi][ni][1])
                        : "r"(a[mi][0]), "r"(a[mi][1]), "r"(a[mi][2]), "r"(a[mi][3]),
                          "r"(b[p][o]), "r"(b[p][o + 1]));
                }
            }
        }

        if (kt + 2 < NK) issue_tile(kt + 2);
        else asm volatile("cp.async.commit_group;");
    }

    // ---- epilogue: (logit - y)^2 ----
    const int gr = lane >> 2;
    const int gc = (lane & 3) * 2;
    float acc = 0.0f;
    #pragma unroll
    for (int mi = 0; mi < 4; mi++) {
        int gn0 = n_blk + warp_m * 64 + mi * 16 + gr;
        const float* y0 = y + (size_t)gn0 * V_DIM + v_blk;
        const float* y8 = y0 + (size_t)8 * V_DIM;
        #pragma unroll
        for (int ni = 0; ni < 4; ni++) {
            int col = warp_n * 32 + ni * 8 + gc;
            float2 y01 = *(const float2*)(y0 + col);
            float2 y23 = *(const float2*)(y8 + col);
            float2 c01 = __half22float2(*(__half2*)&c[mi][ni][0]);
            float2 c23 = __half22float2(*(__half2*)&c[mi][ni][1]);
            float d0 = c01.x - y01.x;
            float d1 = c01.y - y01.y;
            float d2 = c23.x - y23.x;
            float d3 = c23.y - y23.y;
            acc += d0 * d0 + d1 * d1 + d2 * d2 + d3 * d3;
        }
    }
    #pragma unroll
    for (int off = 16; off; off >>= 1)
        acc += __shfl_xor_sync(0xFFFFFFFFu, acc, off);
    if (lane == 0) red[warp] = acc;
    __syncthreads();
    if (warp == 0) {
        float sv = (lane < 8) ? red[lane] : 0.0f;
        #pragma unroll
        for (int off = 4; off; off >>= 1)
            sv += __shfl_xor_sync(0xFFFFFFFFu, sv, off);
        if (lane == 0) {
            atomicAdd(&g_acc, (double)sv);
            __threadfence();
            unsigned done = atomicAdd(&g_count, 1u);
            if (done == NUM_CTAS - 1) {
                double total = atomicAdd(&g_acc, 0.0);   // ordered read
                out[0] = (float)(total / ((double)N_DIM * (double)V_DIM));
                g_count = 0;   // reset for next graph replay
            }
        }
    }
}

// ============================================================
extern "C" void kernel_launch(void* const* d_in, const int* in_sizes, int n_in,
                              void* d_out, int out_size) {
    (void)in_sizes; (void)n_in; (void)out_size;
    const float* x = (const float*)d_in[0];   // [N, H]
    const float* y = (const float*)d_in[1];   // [N, V]
    const float* W = (const float*)d_in[2];   // [V, H]
    float* out = (float*)d_out;

    static bool attr_set = false;
    if (!attr_set) {
        cudaFuncSetAttribute(gemm_mse_kernel,
                             cudaFuncAttributeMaxDynamicSharedMemorySize,
                             SMEM_BYTES);
        attr_set = true;
    }

    convert_kernel<<<2048, 256>>>(x, W);

    dim3 grid(N_DIM / BM, V_DIM / BN);  // (16, 250): x-fastest -> W stripe L2 reuse
    gemm_mse_kernel<<<grid, THREADS, SMEM_BYTES>>>(y, out);
}